// round 14
// baseline (speedup 1.0000x reference)
#include <cuda_runtime.h>

// SoftRank via bucket-histogram rank + narrow tanh window.
// out[b,j,c] = (1/N) * sum_i sigmoid(1000*(x[b,j,c]-x[b,i,c]))
//
// Best-measured configuration (R8): linear 4096 buckets, W=0.0045,
// computed per-element bucket bounds, own-element epilogue.
//
// Per (b,c) column (one CTA, 1024 threads):
//   1. histogram 1024 values into 4096 buckets over [-5,5] (smem atomics)
//   2. block exclusive prefix sum, 4 buckets/thread (uint4), all warps
//      redundantly scan the warp totals, sentinel cnt[4096]=N
//   3. scatter values into bucket order
//   4. own-element epilogue: rank = prefix of lower buckets (each contributes
//      exactly 1; aggregate tail err ~ rho*e^-4.5/1000 ~ 4.7e-6, validated),
//      plus branchless tanh.approx scan of the small bucket window
//      (saturation keeps out-of-window scanned elements exact).

#define NN       1024
#define CC       16
#define BB       8
#define NBKT     4096
#define RANGE_LO (-5.0f)
#define INV_W    409.6f          // NBKT / 10.0
#define WINDOW   0.0045f         // cutoff arg >= 4.5 -> rel err ~5e-6

__device__ __forceinline__ float fast_tanh(float x) {
    float r;
    asm("tanh.approx.f32 %0, %1;" : "=f"(r) : "f"(x));
    return r;
}

__device__ __forceinline__ int bucket_of(float v) {
    int b = (int)((v - RANGE_LO) * INV_W);
    return min(max(b, 0), NBKT - 1);
}

__global__ __launch_bounds__(NN) void softrank_final_kernel(
    const float* __restrict__ x, float* __restrict__ out)
{
    const int b = blockIdx.x >> 4;       // / CC
    const int c = blockIdx.x & (CC - 1); // % CC

    __shared__ unsigned cnt[NBKT + 4];   // counts -> exclusive prefix; [NBKT]=N sentinel
    __shared__ float    skey[NN];        // values in bucket order
    __shared__ unsigned wsum[32];

    const int t    = threadIdx.x;
    const int lane = t & 31;
    const int wid  = t >> 5;

    const float v = x[(b * NN + t) * CC + c];   // long-latency, issued first
    ((uint4*)cnt)[t] = make_uint4(0u, 0u, 0u, 0u);
    const int bk = bucket_of(v);
    __syncthreads();

    // ---- histogram; slot = within-bucket ordinal ----
    const unsigned slot = atomicAdd(&cnt[bk], 1u);
    __syncthreads();

    // ---- block exclusive prefix sum over 4096 counts, 4 per thread ----
    const uint4 c4 = ((uint4*)cnt)[t];
    const unsigned tsum = c4.x + c4.y + c4.z + c4.w;

    unsigned inc = tsum;                 // warp-inclusive scan of thread sums
    #pragma unroll
    for (int j = 1; j < 32; j <<= 1) {
        unsigned n = __shfl_up_sync(0xffffffffu, inc, j);
        if (lane >= j) inc += n;
    }
    if (lane == 31) wsum[wid] = inc;
    __syncthreads();

    // every warp redundantly scans the 32 warp totals (no wid-0 wait)
    unsigned wv = wsum[lane];
    unsigned wi = wv;
    #pragma unroll
    for (int j = 1; j < 32; j <<= 1) {
        unsigned n = __shfl_up_sync(0xffffffffu, wi, j);
        if (lane >= j) wi += n;
    }
    const unsigned wexcl = __shfl_sync(0xffffffffu, wi - wv, wid);

    const unsigned texcl = wexcl + (inc - tsum);
    uint4 p4;
    p4.x = texcl;
    p4.y = texcl + c4.x;
    p4.z = texcl + c4.x + c4.y;
    p4.w = texcl + c4.x + c4.y + c4.z;
    ((uint4*)cnt)[t] = p4;
    if (t == 0) cnt[NBKT] = (unsigned)NN;        // branchless end lookup
    __syncthreads();

    // ---- scatter into bucket order ----
    skey[cnt[bk] + slot] = v;
    __syncthreads();

    // ---- own-element epilogue, computed window bounds ----
    const int b_lo = bucket_of(v - WINDOW);
    const int b_hi = bucket_of(v + WINDOW);

    const unsigned start = cnt[b_lo];
    const unsigned end   = cnt[b_hi + 1];

    const float a = 500.0f * v;
    float s0 = 0.0f, s1 = 0.0f;
    unsigned i = start;
    for (; i + 1 < end; i += 2) {        // 2-way ILP on LDS + MUFU
        s0 += fast_tanh(fmaf(-500.0f, skey[i],     a));
        s1 += fast_tanh(fmaf(-500.0f, skey[i + 1], a));
    }
    if (i < end)
        s0 += fast_tanh(fmaf(-500.0f, skey[i], a));

    const float sum = (float)start
                    + 0.5f * (float)(end - start)
                    + 0.5f * (s0 + s1);

    out[(b * NN + t) * CC + c] = sum * (1.0f / (float)NN);
}

extern "C" void kernel_launch(void* const* d_in, const int* in_sizes, int n_in,
                              void* d_out, int out_size)
{
    const float* x = (const float*)d_in[0];
    float* out = (float*)d_out;
    softrank_final_kernel<<<BB * CC, NN>>>(x, out);
}

// round 15
// speedup vs baseline: 3.2981x; 3.2981x over previous
#include <cuda_runtime.h>

// SoftRank via bucket-histogram rank + narrow tanh window.
// out[b,j,c] = (1/N) * sum_i sigmoid(1000*(x[b,j,c]-x[b,i,c]))
//
// Validated-optimal skeleton (R8/R13): linear 4096 buckets, computed
// per-element bucket bounds, own-element epilogue. W tightened to 0.003
// (cutoff arg 3 -> aggregate tail err ~2e-5, calibrated model).
//
// Per (b,c) column (one CTA, 1024 threads):
//   1. histogram 1024 values into 4096 buckets over [-5,5] (smem atomics)
//   2. block exclusive prefix sum, 4 buckets/thread (uint4), all warps
//      redundantly scan the warp totals, sentinel cnt[4096]=N
//   3. scatter values into bucket order
//   4. own-element epilogue: rank = prefix of lower buckets (each contributes
//      exactly 1 up to the tail model), plus branchless tanh.approx scan of
//      the ~2.5-element bucket window (saturation keeps out-of-window
//      scanned elements exact).

#define NN       1024
#define CC       16
#define BB       8
#define NBKT     4096
#define RANGE_LO (-5.0f)
#define INV_W    409.6f          // NBKT / 10.0
#define WINDOW   0.003f          // cutoff arg >= 3 -> rel err ~2e-5

__device__ __forceinline__ float fast_tanh(float x) {
    float r;
    asm("tanh.approx.f32 %0, %1;" : "=f"(r) : "f"(x));
    return r;
}

__device__ __forceinline__ int bucket_of(float v) {
    int b = (int)((v - RANGE_LO) * INV_W);
    return min(max(b, 0), NBKT - 1);
}

__global__ __launch_bounds__(NN) void softrank_final2_kernel(
    const float* __restrict__ x, float* __restrict__ out)
{
    const int b = blockIdx.x >> 4;       // / CC
    const int c = blockIdx.x & (CC - 1); // % CC

    __shared__ unsigned cnt[NBKT + 4];   // counts -> exclusive prefix; [NBKT]=N sentinel
    __shared__ float    skey[NN];        // values in bucket order
    __shared__ unsigned wsum[32];

    const int t    = threadIdx.x;
    const int lane = t & 31;
    const int wid  = t >> 5;

    const float v = x[(b * NN + t) * CC + c];   // long-latency, issued first
    ((uint4*)cnt)[t] = make_uint4(0u, 0u, 0u, 0u);
    const int bk = bucket_of(v);
    __syncthreads();

    // ---- histogram; slot = within-bucket ordinal ----
    const unsigned slot = atomicAdd(&cnt[bk], 1u);
    __syncthreads();

    // ---- block exclusive prefix sum over 4096 counts, 4 per thread ----
    const uint4 c4 = ((uint4*)cnt)[t];
    const unsigned tsum = c4.x + c4.y + c4.z + c4.w;

    unsigned inc = tsum;                 // warp-inclusive scan of thread sums
    #pragma unroll
    for (int j = 1; j < 32; j <<= 1) {
        unsigned n = __shfl_up_sync(0xffffffffu, inc, j);
        if (lane >= j) inc += n;
    }
    if (lane == 31) wsum[wid] = inc;
    __syncthreads();

    // every warp redundantly scans the 32 warp totals (no wid-0 wait)
    unsigned wv = wsum[lane];
    unsigned wi = wv;
    #pragma unroll
    for (int j = 1; j < 32; j <<= 1) {
        unsigned n = __shfl_up_sync(0xffffffffu, wi, j);
        if (lane >= j) wi += n;
    }
    const unsigned wexcl = __shfl_sync(0xffffffffu, wi - wv, wid);

    const unsigned texcl = wexcl + (inc - tsum);
    uint4 p4;
    p4.x = texcl;
    p4.y = texcl + c4.x;
    p4.z = texcl + c4.x + c4.y;
    p4.w = texcl + c4.x + c4.y + c4.z;
    ((uint4*)cnt)[t] = p4;
    if (t == 0) cnt[NBKT] = (unsigned)NN;        // branchless end lookup
    __syncthreads();

    // ---- scatter into bucket order ----
    skey[cnt[bk] + slot] = v;
    __syncthreads();

    // ---- own-element epilogue, computed window bounds ----
    const int b_lo = bucket_of(v - WINDOW);
    const int b_hi = bucket_of(v + WINDOW);

    const unsigned start = cnt[b_lo];
    const unsigned end   = cnt[b_hi + 1];

    const float a = 500.0f * v;
    float s0 = 0.0f, s1 = 0.0f;
    unsigned i = start;
    for (; i + 1 < end; i += 2) {        // 2-way ILP on LDS + MUFU
        s0 += fast_tanh(fmaf(-500.0f, skey[i],     a));
        s1 += fast_tanh(fmaf(-500.0f, skey[i + 1], a));
    }
    if (i < end)
        s0 += fast_tanh(fmaf(-500.0f, skey[i], a));

    const float sum = (float)start
                    + 0.5f * (float)(end - start)
                    + 0.5f * (s0 + s1);

    out[(b * NN + t) * CC + c] = sum * (1.0f / (float)NN);
}

extern "C" void kernel_launch(void* const* d_in, const int* in_sizes, int n_in,
                              void* d_out, int out_size)
{
    const float* x = (const float*)d_in[0];
    float* out = (float*)d_out;
    softrank_final2_kernel<<<BB * CC, NN>>>(x, out);
}